// round 17
// baseline (speedup 1.0000x reference)
#include <cuda_runtime.h>
#include <cuda_fp16.h>
#include <cstdint>

// MeanAggregator: out[n,:] = mean over valid neighbors of features[idx[n,k],:]
// features: [60000,128] f32. idx: [10000,64] (int64/int32). mask: [10000,64]
// (byte/int32). out: [10000,128] f32.
//
// Kernel 1: f32 table -> fp16 shadow (static scratch, 15.4MB) + dtype flags.
// Kernel 2: TWO nodes per warp, chunks interleaved (8 loads node A + 8 loads
// node B in flight together) so each node's drain is filled by the other's
// work and per-node setup cost is amortized; grid halves to ~1.1 waves.
// 256B fp16 rows, lane = 8B uint2. HADD2 accumulation, 4 rotating half2
// pairs per node (depth <= 16 rows, measured ~5e-4 rel err vs 1e-3 gate).
// Compaction stores pre-scaled row bases (r*32). Dual-arm liveness trick on
// all full-chunk loops keeps loads front-batched.

#define K_NEIGH 64
#define N_SRC_MAX 60000
#define WARPS_PER_BLOCK 8

__device__ uint2 g_htab[(size_t)N_SRC_MAX * 32];   // fp16 table, row=32 x 8B
__device__ int g_idx_is64;
__device__ int g_mask_is32;

__global__ __launch_bounds__(256) void convert_kernel(
    const float4* __restrict__ feat,
    const int* __restrict__ idx_words,
    const unsigned char* __restrict__ mask_bytes,
    int n_elem)
{
    if (blockIdx.x == 0 && threadIdx.x < 32) {
        const int lane = threadIdx.x;
        int v = 0;
        #pragma unroll
        for (int r = 0; r < 4; r++) v |= idx_words[2 * (lane + 32 * r) + 1];
        unsigned idx_nz = __ballot_sync(0xffffffffu, v != 0);
        int m = 0;
        #pragma unroll
        for (int r = 0; r < 4; r++) {
            int p = lane + 32 * r;
            if ((p & 3) != 0) m |= mask_bytes[p];
        }
        unsigned msk_nz = __ballot_sync(0xffffffffu, m != 0);
        if (lane == 0) {
            g_idx_is64  = (idx_nz == 0) ? 1 : 0;
            g_mask_is32 = (msk_nz == 0) ? 1 : 0;
        }
    }

    int i = blockIdx.x * blockDim.x + threadIdx.x;
    const int stride = gridDim.x * blockDim.x;
    for (; i < n_elem; i += stride) {
        float4 f = __ldg(&feat[i]);
        __half2 lo = __floats2half2_rn(f.x, f.y);
        __half2 hi = __floats2half2_rn(f.z, f.w);
        uint2 u;
        u.x = *reinterpret_cast<const unsigned*>(&lo);
        u.y = *reinterpret_cast<const unsigned*>(&hi);
        g_htab[i] = u;
    }
}

__device__ __forceinline__ __half2 lo2(uint2 q) { return *reinterpret_cast<__half2*>(&q.x); }
__device__ __forceinline__ __half2 hi2(uint2 q) { return *reinterpret_cast<__half2*>(&q.y); }

// Accumulate one row (uint2 = 4 halves low dims + 4 high) into pair `rot`.
#define ACCR(S, Q, ROT) do { \
    S[ROT] = __hadd2(S[ROT], lo2(Q)); \
    S[4 + (ROT)] = __hadd2(S[4 + (ROT)], hi2(Q)); \
} while (0)

__global__ __launch_bounds__(256) void mean_agg_kernel(
    const void* __restrict__ nidx,
    const void* __restrict__ nmask,
    float4* __restrict__ out,
    int n_nodes)
{
    __shared__ int srows[WARPS_PER_BLOCK][128];   // [0..63] node A, [64..127] node B

    const int warp = threadIdx.x >> 5;
    const int lane = threadIdx.x & 31;
    const int gw   = blockIdx.x * WARPS_PER_BLOCK + warp;
    const int nA   = 2 * gw;
    if (nA >= n_nodes) return;
    const int nB   = nA + 1;
    const int hasB = (nB < n_nodes);

    const size_t baseA = (size_t)nA * K_NEIGH;
    const size_t baseB = hasB ? (size_t)nB * K_NEIGH : baseA;

    int iA0, iA1, iB0, iB1;
    if (g_idx_is64) {
        const long long* pa = (const long long*)nidx + baseA;
        const long long* pb = (const long long*)nidx + baseB;
        iA0 = (int)pa[lane]; iA1 = (int)pa[lane + 32];
        iB0 = (int)pb[lane]; iB1 = (int)pb[lane + 32];
    } else {
        const int* pa = (const int*)nidx + baseA;
        const int* pb = (const int*)nidx + baseB;
        iA0 = pa[lane]; iA1 = pa[lane + 32];
        iB0 = pb[lane]; iB1 = pb[lane + 32];
    }

    int mA0, mA1, mB0, mB1;
    if (g_mask_is32) {
        const int* pa = (const int*)nmask + baseA;
        const int* pb = (const int*)nmask + baseB;
        mA0 = (pa[lane] != 0); mA1 = (pa[lane + 32] != 0);
        mB0 = (pb[lane] != 0); mB1 = (pb[lane + 32] != 0);
    } else {
        const unsigned char* pa = (const unsigned char*)nmask + baseA;
        const unsigned char* pb = (const unsigned char*)nmask + baseB;
        mA0 = (pa[lane] != 0); mA1 = (pa[lane + 32] != 0);
        mB0 = (pb[lane] != 0); mB1 = (pb[lane + 32] != 0);
    }
    if (!hasB) { mB0 = 0; mB1 = 0; }

    const unsigned bA0 = __ballot_sync(0xffffffffu, mA0);
    const unsigned bA1 = __ballot_sync(0xffffffffu, mA1);
    const unsigned bB0 = __ballot_sync(0xffffffffu, mB0);
    const unsigned bB1 = __ballot_sync(0xffffffffu, mB1);
    const int cA0 = __popc(bA0), cntA = cA0 + __popc(bA1);
    const int cB0 = __popc(bB0), cntB = cB0 + __popc(bB1);

    // Warp-compact pre-scaled row bases (r*32) for both nodes.
    const unsigned lt = (1u << lane) - 1u;
    if (mA0) srows[warp][__popc(bA0 & lt)] = iA0 * 32;
    if (mA1) srows[warp][cA0 + __popc(bA1 & lt)] = iA1 * 32;
    if (mB0) srows[warp][64 + __popc(bB0 & lt)] = iB0 * 32;
    if (mB1) srows[warp][64 + cB0 + __popc(bB1 & lt)] = iB1 * 32;
    __syncwarp();

    const __half2 hz = __float2half2_rn(0.f);
    __half2 sA[8] = {hz, hz, hz, hz, hz, hz, hz, hz};
    __half2 sB[8] = {hz, hz, hz, hz, hz, hz, hz, hz};

    const unsigned laneu = (unsigned)lane;
    const int fullA = cntA & ~7;
    const int fullB = cntB & ~7;
    const int nBoth = (fullA < fullB) ? fullA : fullB;

    int j = 0;
    for (; j < nBoth; j += 8) {
        int a0 = srows[warp][j+0], a1 = srows[warp][j+1];
        int a2 = srows[warp][j+2], a3 = srows[warp][j+3];
        int a4 = srows[warp][j+4], a5 = srows[warp][j+5];
        int a6 = srows[warp][j+6], a7 = srows[warp][j+7];
        int b0 = srows[warp][64+j+0], b1 = srows[warp][64+j+1];
        int b2 = srows[warp][64+j+2], b3 = srows[warp][64+j+3];
        int b4 = srows[warp][64+j+4], b5 = srows[warp][64+j+5];
        int b6 = srows[warp][64+j+6], b7 = srows[warp][64+j+7];

        // 16 independent gathers in flight (8 per node).
        uint2 qa0 = __ldg(&g_htab[(unsigned)a0 + laneu]);
        uint2 qa1 = __ldg(&g_htab[(unsigned)a1 + laneu]);
        uint2 qa2 = __ldg(&g_htab[(unsigned)a2 + laneu]);
        uint2 qa3 = __ldg(&g_htab[(unsigned)a3 + laneu]);
        uint2 qa4 = __ldg(&g_htab[(unsigned)a4 + laneu]);
        uint2 qa5 = __ldg(&g_htab[(unsigned)a5 + laneu]);
        uint2 qa6 = __ldg(&g_htab[(unsigned)a6 + laneu]);
        uint2 qa7 = __ldg(&g_htab[(unsigned)a7 + laneu]);
        uint2 qb0 = __ldg(&g_htab[(unsigned)b0 + laneu]);
        uint2 qb1 = __ldg(&g_htab[(unsigned)b1 + laneu]);
        uint2 qb2 = __ldg(&g_htab[(unsigned)b2 + laneu]);
        uint2 qb3 = __ldg(&g_htab[(unsigned)b3 + laneu]);
        uint2 qb4 = __ldg(&g_htab[(unsigned)b4 + laneu]);
        uint2 qb5 = __ldg(&g_htab[(unsigned)b5 + laneu]);
        uint2 qb6 = __ldg(&g_htab[(unsigned)b6 + laneu]);
        uint2 qb7 = __ldg(&g_htab[(unsigned)b7 + laneu]);

        // Dual consumer arms keep all 16 loads live across the branch.
        if (j + 8 <= cntA) {   // always true here; compiler can't prove it
            ACCR(sA, qa0, 0); ACCR(sA, qa1, 1); ACCR(sA, qa2, 2); ACCR(sA, qa3, 3);
            ACCR(sA, qa4, 0); ACCR(sA, qa5, 1); ACCR(sA, qa6, 2); ACCR(sA, qa7, 3);
            ACCR(sB, qb0, 0); ACCR(sB, qb1, 1); ACCR(sB, qb2, 2); ACCR(sB, qb3, 3);
            ACCR(sB, qb4, 0); ACCR(sB, qb5, 1); ACCR(sB, qb6, 2); ACCR(sB, qb7, 3);
        } else {
            // never executed; touches every q to keep loads batched
            sA[0] = __hadd2(sA[0], hi2(qa0)); sA[1] = __hadd2(sA[1], hi2(qa1));
            sA[2] = __hadd2(sA[2], hi2(qa2)); sA[3] = __hadd2(sA[3], hi2(qa3));
            sA[4] = __hadd2(sA[4], lo2(qa4)); sA[5] = __hadd2(sA[5], lo2(qa5));
            sA[6] = __hadd2(sA[6], lo2(qa6)); sA[7] = __hadd2(sA[7], lo2(qa7));
            sB[0] = __hadd2(sB[0], hi2(qb0)); sB[1] = __hadd2(sB[1], hi2(qb1));
            sB[2] = __hadd2(sB[2], hi2(qb2)); sB[3] = __hadd2(sB[3], hi2(qb3));
            sB[4] = __hadd2(sB[4], lo2(qb4)); sB[5] = __hadd2(sB[5], lo2(qb5));
            sB[6] = __hadd2(sB[6], lo2(qb6)); sB[7] = __hadd2(sB[7], lo2(qb7));
        }
    }

    // Leftover full 8-chunks (only one of these loops runs).
    for (int ja = j; ja < fullA; ja += 8) {
        int a0 = srows[warp][ja+0], a1 = srows[warp][ja+1];
        int a2 = srows[warp][ja+2], a3 = srows[warp][ja+3];
        int a4 = srows[warp][ja+4], a5 = srows[warp][ja+5];
        int a6 = srows[warp][ja+6], a7 = srows[warp][ja+7];
        uint2 q0 = __ldg(&g_htab[(unsigned)a0 + laneu]);
        uint2 q1 = __ldg(&g_htab[(unsigned)a1 + laneu]);
        uint2 q2 = __ldg(&g_htab[(unsigned)a2 + laneu]);
        uint2 q3 = __ldg(&g_htab[(unsigned)a3 + laneu]);
        uint2 q4 = __ldg(&g_htab[(unsigned)a4 + laneu]);
        uint2 q5 = __ldg(&g_htab[(unsigned)a5 + laneu]);
        uint2 q6 = __ldg(&g_htab[(unsigned)a6 + laneu]);
        uint2 q7 = __ldg(&g_htab[(unsigned)a7 + laneu]);
        if (ja + 8 <= cntA) {
            ACCR(sA, q0, 0); ACCR(sA, q1, 1); ACCR(sA, q2, 2); ACCR(sA, q3, 3);
            ACCR(sA, q4, 0); ACCR(sA, q5, 1); ACCR(sA, q6, 2); ACCR(sA, q7, 3);
        } else {
            sA[0] = __hadd2(sA[0], hi2(q0)); sA[1] = __hadd2(sA[1], hi2(q1));
            sA[2] = __hadd2(sA[2], hi2(q2)); sA[3] = __hadd2(sA[3], hi2(q3));
            sA[4] = __hadd2(sA[4], lo2(q4)); sA[5] = __hadd2(sA[5], lo2(q5));
            sA[6] = __hadd2(sA[6], lo2(q6)); sA[7] = __hadd2(sA[7], lo2(q7));
        }
    }
    for (int jb = j; jb < fullB; jb += 8) {
        int b0 = srows[warp][64+jb+0], b1 = srows[warp][64+jb+1];
        int b2 = srows[warp][64+jb+2], b3 = srows[warp][64+jb+3];
        int b4 = srows[warp][64+jb+4], b5 = srows[warp][64+jb+5];
        int b6 = srows[warp][64+jb+6], b7 = srows[warp][64+jb+7];
        uint2 q0 = __ldg(&g_htab[(unsigned)b0 + laneu]);
        uint2 q1 = __ldg(&g_htab[(unsigned)b1 + laneu]);
        uint2 q2 = __ldg(&g_htab[(unsigned)b2 + laneu]);
        uint2 q3 = __ldg(&g_htab[(unsigned)b3 + laneu]);
        uint2 q4 = __ldg(&g_htab[(unsigned)b4 + laneu]);
        uint2 q5 = __ldg(&g_htab[(unsigned)b5 + laneu]);
        uint2 q6 = __ldg(&g_htab[(unsigned)b6 + laneu]);
        uint2 q7 = __ldg(&g_htab[(unsigned)b7 + laneu]);
        if (jb + 8 <= cntB) {
            ACCR(sB, q0, 0); ACCR(sB, q1, 1); ACCR(sB, q2, 2); ACCR(sB, q3, 3);
            ACCR(sB, q4, 0); ACCR(sB, q5, 1); ACCR(sB, q6, 2); ACCR(sB, q7, 3);
        } else {
            sB[0] = __hadd2(sB[0], hi2(q0)); sB[1] = __hadd2(sB[1], hi2(q1));
            sB[2] = __hadd2(sB[2], hi2(q2)); sB[3] = __hadd2(sB[3], hi2(q3));
            sB[4] = __hadd2(sB[4], lo2(q4)); sB[5] = __hadd2(sB[5], lo2(q5));
            sB[6] = __hadd2(sB[6], lo2(q6)); sB[7] = __hadd2(sB[7], lo2(q7));
        }
    }

    // Tails (0..7 rows each), predicated loads (exact fp16 +0 when off).
    const uint2 z = make_uint2(0u, 0u);
    const int remA = cntA & 7;
    if (remA) {
        int t0 = srows[warp][fullA + 0];
        int t1 = (remA > 1) ? srows[warp][fullA + 1] : 0;
        int t2 = (remA > 2) ? srows[warp][fullA + 2] : 0;
        int t3 = (remA > 3) ? srows[warp][fullA + 3] : 0;
        int t4 = (remA > 4) ? srows[warp][fullA + 4] : 0;
        int t5 = (remA > 5) ? srows[warp][fullA + 5] : 0;
        int t6 = (remA > 6) ? srows[warp][fullA + 6] : 0;
        uint2 g0 = __ldg(&g_htab[(unsigned)t0 + laneu]);
        uint2 g1 = z; if (remA > 1) g1 = __ldg(&g_htab[(unsigned)t1 + laneu]);
        uint2 g2 = z; if (remA > 2) g2 = __ldg(&g_htab[(unsigned)t2 + laneu]);
        uint2 g3 = z; if (remA > 3) g3 = __ldg(&g_htab[(unsigned)t3 + laneu]);
        uint2 g4 = z; if (remA > 4) g4 = __ldg(&g_htab[(unsigned)t4 + laneu]);
        uint2 g5 = z; if (remA > 5) g5 = __ldg(&g_htab[(unsigned)t5 + laneu]);
        uint2 g6 = z; if (remA > 6) g6 = __ldg(&g_htab[(unsigned)t6 + laneu]);
        ACCR(sA, g0, 0); ACCR(sA, g1, 1); ACCR(sA, g2, 2); ACCR(sA, g3, 3);
        ACCR(sA, g4, 0); ACCR(sA, g5, 1); ACCR(sA, g6, 2);
    }
    const int remB = cntB & 7;
    if (remB) {
        int t0 = srows[warp][64 + fullB + 0];
        int t1 = (remB > 1) ? srows[warp][64 + fullB + 1] : 0;
        int t2 = (remB > 2) ? srows[warp][64 + fullB + 2] : 0;
        int t3 = (remB > 3) ? srows[warp][64 + fullB + 3] : 0;
        int t4 = (remB > 4) ? srows[warp][64 + fullB + 4] : 0;
        int t5 = (remB > 5) ? srows[warp][64 + fullB + 5] : 0;
        int t6 = (remB > 6) ? srows[warp][64 + fullB + 6] : 0;
        uint2 g0 = __ldg(&g_htab[(unsigned)t0 + laneu]);
        uint2 g1 = z; if (remB > 1) g1 = __ldg(&g_htab[(unsigned)t1 + laneu]);
        uint2 g2 = z; if (remB > 2) g2 = __ldg(&g_htab[(unsigned)t2 + laneu]);
        uint2 g3 = z; if (remB > 3) g3 = __ldg(&g_htab[(unsigned)t3 + laneu]);
        uint2 g4 = z; if (remB > 4) g4 = __ldg(&g_htab[(unsigned)t4 + laneu]);
        uint2 g5 = z; if (remB > 5) g5 = __ldg(&g_htab[(unsigned)t5 + laneu]);
        uint2 g6 = z; if (remB > 6) g6 = __ldg(&g_htab[(unsigned)t6 + laneu]);
        ACCR(sB, g0, 0); ACCR(sB, g1, 1); ACCR(sB, g2, 2); ACCR(sB, g3, 3);
        ACCR(sB, g4, 0); ACCR(sB, g5, 1); ACCR(sB, g6, 2);
    }

    // Epilogue: combine pairs, promote once, write one row per node.
    {
        float2 f0 = __half22float2(sA[0]), f1 = __half22float2(sA[1]);
        float2 f2 = __half22float2(sA[2]), f3 = __half22float2(sA[3]);
        float2 h0 = __half22float2(sA[4]), h1 = __half22float2(sA[5]);
        float2 h2 = __half22float2(sA[6]), h3 = __half22float2(sA[7]);
        const float inv = (cntA > 0) ? (1.0f / (float)cntA) : 0.0f;
        float4 r;
        r.x = ((f0.x + f1.x) + (f2.x + f3.x)) * inv;
        r.y = ((f0.y + f1.y) + (f2.y + f3.y)) * inv;
        r.z = ((h0.x + h1.x) + (h2.x + h3.x)) * inv;
        r.w = ((h0.y + h1.y) + (h2.y + h3.y)) * inv;
        out[(size_t)nA * 32 + lane] = r;
    }
    if (hasB) {
        float2 f0 = __half22float2(sB[0]), f1 = __half22float2(sB[1]);
        float2 f2 = __half22float2(sB[2]), f3 = __half22float2(sB[3]);
        float2 h0 = __half22float2(sB[4]), h1 = __half22float2(sB[5]);
        float2 h2 = __half22float2(sB[6]), h3 = __half22float2(sB[7]);
        const float inv = (cntB > 0) ? (1.0f / (float)cntB) : 0.0f;
        float4 r;
        r.x = ((f0.x + f1.x) + (f2.x + f3.x)) * inv;
        r.y = ((f0.y + f1.y) + (f2.y + f3.y)) * inv;
        r.z = ((h0.x + h1.x) + (h2.x + h3.x)) * inv;
        r.w = ((h0.y + h1.y) + (h2.y + h3.y)) * inv;
        out[(size_t)nB * 32 + lane] = r;
    }
}

extern "C" void kernel_launch(void* const* d_in, const int* in_sizes, int n_in,
                              void* d_out, int out_size)
{
    const float* feat  = (const float*)d_in[0];
    const void*  nidx  = d_in[1];
    const void*  nmask = d_in[2];
    float* out = (float*)d_out;

    const int n_elem  = in_sizes[0] / 4;          // float4 count = n_src*32
    const int n_nodes = in_sizes[1] / K_NEIGH;    // 10000

    convert_kernel<<<1184, 256>>>((const float4*)feat, (const int*)nidx,
                                  (const unsigned char*)nmask, n_elem);

    const int threads = 32 * WARPS_PER_BLOCK;
    const int pairs = (n_nodes + 1) / 2;
    int blocks = (pairs + WARPS_PER_BLOCK - 1) / WARPS_PER_BLOCK;
    mean_agg_kernel<<<blocks, threads>>>(nidx, nmask, (float4*)out, n_nodes);
}